// round 15
// baseline (speedup 1.0000x reference)
#include <cuda_runtime.h>
#include <cstdint>

#define BB 8
#define HH 256
#define WW 256
#define NPIX (BB*HH*WW)
#define N_ITERS 200
#define TT 4                 // halo width / sub-iterations per exchange
#define NB (N_ITERS/TT)      // 50 exchange rounds (49 barriers)
#define NCTAS 128            // 8 images * (4x4) 64x64 tiles, 1 CTA/SM
#define NTHREADS 672         // 21 warps; 648 active (36 col-pairs x 18 row groups)
#define NACT 648
#define NGRP 18
#define RPT 4                // rows per thread (x2 cols = 8 cells)
#define EXT 72               // ext region 72x72
#define SH_R 74              // ubS rows: ext rows -1..72 at [1+r]
#define SH_C 76              // ubS cols: ext cols -2..73 at [2+c] (float2-aligned)

// Double-buffered full-state exchange arrays (alloc-free scratch)
__device__ float gU [2][NPIX];
__device__ float gUB[2][NPIX];
__device__ float gP [2][NPIX];
__device__ float gQ [2][NPIX];

// Per-image barrier counters, one 128B line each (zero-initialized).
struct __align__(128) ImgLine { unsigned long long v; unsigned long long pad[15]; };
__device__ ImgLine g_arr[BB];

__device__ __forceinline__ float clipf(float v, float b) {
    return fminf(fmaxf(v, -b), b);
}
__device__ __forceinline__ float ldcg(const float* p) {
    float v;
    asm volatile("ld.global.cg.f32 %0, [%1];" : "=f"(v) : "l"(p) : "memory");
    return v;
}
__device__ __forceinline__ unsigned long long ld_acq(const unsigned long long* p) {
    unsigned long long v;
    asm volatile("ld.acquire.gpu.global.u64 %0, [%1];" : "=l"(v) : "l"(p) : "memory");
    return v;
}
__device__ __forceinline__ void red_rel_add1(unsigned long long* p) {
    asm volatile("red.release.gpu.global.add.u64 [%0], %1;" :: "l"(p), "l"(1ULL) : "memory");
}

__global__ __launch_bounds__(NTHREADS, 1)
void tv_block(const float* __restrict__ f,
              const float* __restrict__ lam,
              float* __restrict__ out)
{
    const float SIG  = 0.35355339f;
    const float TAUc = 0.35355339f;
    const float INV  = 1.0f / (1.0f + TAUc);

    // Double-buffered ubar tile; only cross-thread array in the kernel.
    __shared__ float ubS[2][SH_R][SH_C];   // ~44 KB

    const int cta = blockIdx.x;
    const int img = cta >> 4;
    const int t   = cta & 15;
    const int i0  = (t >> 2) * 64;
    const int j0  = (t & 3) * 64;
    const int tid = threadIdx.x;
    const bool act = (tid < NACT);
    const int cp  = tid % 36;          // column pair 0..35
    const int rg  = tid / 36;          // row group 0..17
    const int rb  = rg * RPT;
    const int c0  = 2 * cp;

    const int gi_top = i0 - TT + rb;
    const int gj0    = j0 - TT + c0;
    const int base   = (img * HH + gi_top) * WW + gj0;

    unsigned long long epoch = 0;
    if (tid == 0) epoch = *(volatile unsigned long long*)&g_arr[img].v;

    // Zero ubS (pads stay 0 forever; border garbage is contamination-tolerated)
    for (int x = tid; x < 2 * SH_R * SH_C; x += NTHREADS) ((float*)ubS)[x] = 0.f;

    // ---- per-cell state + shadow duals in registers (n = 2k+e) ----
    float u[8], ub[8], p[8], q[8], fv[8], lx[8], ly[8];
    float qL[RPT], lamL[RPT], puT[2], lamPT[2];
    if (act) {
#pragma unroll
        for (int k = 0; k < RPT; k++) {
#pragma unroll
            for (int e = 0; e < 2; e++) {
                const int n  = 2 * k + e;
                const int gi = gi_top + k, gj = gj0 + e;
                const bool ii = (gi >= 0 && gi < HH && gj >= 0 && gj < WW);
                const int idx = base + k * WW + e;
                const float fk = ii ? f[idx] : 0.f;
                fv[n] = fk; u[n] = fk; ub[n] = fk; p[n] = 0.f; q[n] = 0.f;
                lx[n] = (ii && gi < HH - 1) ? lam[idx + WW] : 0.f;  // bound p(r,c)
                ly[n] = (ii && gj < WW - 1) ? lam[idx + 1]  : 0.f;  // bound q(r,c)
            }
            qL[k] = 0.f;
            const int gi = gi_top + k;
            // bound for q(r, c0-1) = lam(gi, gj0), exists iff gj0-1 in [0, W-1)
            lamL[k] = (gi >= 0 && gi < HH && gj0 >= 1 && gj0 < WW)
                        ? lam[base + k * WW] : 0.f;
        }
#pragma unroll
        for (int e = 0; e < 2; e++) {
            puT[e] = 0.f;
            const int gj = gj0 + e;
            // bound for p(rb-1, c) = lam(gi_top, gj), exists iff gi_top-1 in [0, H-1)
            lamPT[e] = (gi_top >= 1 && gi_top < HH && gj >= 0 && gj < WW)
                         ? lam[base + e] : 0.f;
        }
    }
    __syncthreads();

#pragma unroll 1
    for (int blk = 0; blk < NB; blk++) {
        if (blk) {
            const int sb = blk & 1;
            // ---- publish interior frame (width-TT band inside true tile) ----
            if (act) {
#pragma unroll
                for (int k = 0; k < RPT; k++) {
#pragma unroll
                    for (int e = 0; e < 2; e++) {
                        const int n = 2 * k + e, r = rb + k, c = c0 + e;
                        const bool interior = (r >= TT && r < EXT - TT &&
                                               c >= TT && c < EXT - TT);
                        if (interior && (r < 2*TT || r >= EXT - 2*TT ||
                                         c < 2*TT || c >= EXT - 2*TT)) {
                            const int idx = base + k * WW + e;
                            gU [sb][idx] = u[n];  gUB[sb][idx] = ub[n];
                            gP [sb][idx] = p[n];  gQ [sb][idx] = q[n];
                        }
                    }
                }
            }
            __threadfence();   // publishes visible GPU-wide before arrive
            __syncthreads();

            // ---- per-image 16-CTA barrier (arrive + spin, monotone) ----
            if (tid == 0) {
                red_rel_add1(&g_arr[img].v);
                const unsigned long long tgt =
                    epoch + 16ULL * (unsigned long long)blk;
                while ((long long)(ld_acq(&g_arr[img].v) - tgt) < 0) { }
            }
            __syncthreads();

            // ---- refresh ring state + shadow duals (registers only) ----
            if (act) {
#pragma unroll
                for (int k = 0; k < RPT; k++) {
#pragma unroll
                    for (int e = 0; e < 2; e++) {
                        const int n = 2 * k + e, r = rb + k, c = c0 + e;
                        const int gi = gi_top + k, gj = gj0 + e;
                        const bool ring = (r < TT || r >= EXT - TT ||
                                           c < TT || c >= EXT - TT);
                        if (ring && gi >= 0 && gi < HH && gj >= 0 && gj < WW) {
                            const int idx = base + k * WW + e;
                            u[n]  = ldcg(&gU [sb][idx]);
                            ub[n] = ldcg(&gUB[sb][idx]);
                            p[n]  = ldcg(&gP [sb][idx]);
                            q[n]  = ldcg(&gQ [sb][idx]);
                        }
                    }
                    {   // shadow qL tracks cell (rb+k, c0-1)
                        const int r = rb + k, cm = c0 - 1;
                        const int gi = gi_top + k, gjm = gj0 - 1;
                        const bool ring = (r < TT || r >= EXT - TT ||
                                           cm < TT || cm >= EXT - TT);
                        if (ring && gi >= 0 && gi < HH && gjm >= 0 && gjm < WW)
                            qL[k] = ldcg(&gQ[sb][base + k * WW - 1]);
                    }
                }
#pragma unroll
                for (int e = 0; e < 2; e++) {   // shadow puT tracks (rb-1, c0+e)
                    const int rm = rb - 1, c = c0 + e;
                    const int gim = gi_top - 1, gj = gj0 + e;
                    const bool ring = (rm < TT || rm >= EXT - TT ||
                                       c < TT || c >= EXT - TT);
                    if (ring && gim >= 0 && gim < HH && gj >= 0 && gj < WW)
                        puT[e] = ldcg(&gP[sb][base + e - WW]);
                }
            }
        }

#pragma unroll 1
        for (int s = 0; s < TT; s++) {
            const int par = s & 1;
            // ---- stage ubar (double-buffered -> single sync suffices) ----
            if (act) {
#pragma unroll
                for (int k = 0; k < RPT; k++)
                    *(float2*)&ubS[par][1 + rb + k][2 + c0] =
                        make_float2(ub[2 * k], ub[2 * k + 1]);
            }
            __syncthreads();   // the ONLY sync per sub-iteration

            if (act) {
                float ubl[RPT], ubr[RPT];
#pragma unroll
                for (int k = 0; k < RPT; k++) {
                    ubl[k] = ubS[par][1 + rb + k][1 + c0];   // ub(r, c0-1)
                    ubr[k] = ubS[par][1 + rb + k][4 + c0];   // ub(r, c0+2)
                }
                const float2 ubA  = *(const float2*)&ubS[par][rb][2 + c0];           // row rb-1
                const float2 ubB2 = *(const float2*)&ubS[par][1 + rb + RPT][2 + c0]; // row rb+RPT

                // ---- dual updates (old ub), incl. shadows ----
                puT[0] = clipf(puT[0] + SIG * (ub[0] - ubA.x), lamPT[0]);
                puT[1] = clipf(puT[1] + SIG * (ub[1] - ubA.y), lamPT[1]);
#pragma unroll
                for (int k = 0; k < RPT; k++) {
                    const int n = 2 * k;
                    const float ub_be = (k < RPT - 1) ? ub[n + 2] : ubB2.x;
                    const float ub_bo = (k < RPT - 1) ? ub[n + 3] : ubB2.y;
                    p[n]     = clipf(p[n]     + SIG * (ub_be     - ub[n]),     lx[n]);
                    p[n + 1] = clipf(p[n + 1] + SIG * (ub_bo     - ub[n + 1]), lx[n + 1]);
                    q[n]     = clipf(q[n]     + SIG * (ub[n + 1] - ub[n]),     ly[n]);
                    q[n + 1] = clipf(q[n + 1] + SIG * (ubr[k]    - ub[n + 1]), ly[n + 1]);
                    qL[k]    = clipf(qL[k]    + SIG * (ub[n]     - ubl[k]),    lamL[k]);
                }

                // ---- primal updates ----
                float pu0 = puT[0], pu1 = puT[1];
#pragma unroll
                for (int k = 0; k < RPT; k++) {
                    const int n = 2 * k;
                    const float d0  = (pu0 - p[n]) + (qL[k] - q[n]);
                    const float un0 = (u[n] + TAUc * (fv[n] - d0)) * INV;
                    ub[n] = 2.f * un0 - u[n];  u[n] = un0;  pu0 = p[n];

                    const float d1  = (pu1 - p[n + 1]) + (q[n] - q[n + 1]);
                    const float un1 = (u[n + 1] + TAUc * (fv[n + 1] - d1)) * INV;
                    ub[n + 1] = 2.f * un1 - u[n + 1];  u[n + 1] = un1;  pu1 = p[n + 1];
                }
            }
        }
    }

    // ---- write interior result ----
    if (act) {
#pragma unroll
        for (int k = 0; k < RPT; k++) {
#pragma unroll
            for (int e = 0; e < 2; e++) {
                const int r = rb + k, c = c0 + e;
                if (r >= TT && r < EXT - TT && c >= TT && c < EXT - TT)
                    out[base + k * WW + e] = u[2 * k + e];
            }
        }
    }
}

extern "C" void kernel_launch(void* const* d_in, const int* in_sizes, int n_in,
                              void* d_out, int out_size) {
    const float* f   = (const float*)d_in[0];
    const float* lam = (const float*)d_in[1];
    float* out = (float*)d_out;

    // Cooperative launch only for co-residency (per-image barrier needs all
    // 16 CTAs of an image resident); no grid.sync used.
    void* args[] = { (void*)&f, (void*)&lam, (void*)&out };
    cudaLaunchCooperativeKernel((void*)tv_block,
                                dim3(NCTAS), dim3(NTHREADS),
                                args, 0, 0);
}